// round 14
// baseline (speedup 1.0000x reference)
#include <cuda_runtime.h>
#include <cstdint>

#define NN 8192
#define FF 64
#define OO 64
#define BM 64                   // rows per CTA (128 threads, 4 warps x m16)
#define SPLITK 4
#define KH (NN / SPLITK)        // 2048
#define NT (KH / 32)            // 64 k-tiles per CTA

// A smem: bf16, 64 rows x 80B (16 data words + 4 pad), 3 stages
#define AROW_B 80
#define ASTG_B (BM * AROW_B)    // 5120
#define NASTG 3
// B smem: bf16, 64 rows x 80B, 5 stages, prefetch distance 4
#define BOFF   (NASTG * ASTG_B) // 15360
#define BSTG_B (64 * AROW_B)    // 5120
#define NBSTG 5
#define PD 4
#define SMEM_MAIN (BOFF + NBSTG * BSTG_B)   // 40960 -> 4 CTAs/SM

// -------------------- scratch --------------------
__device__ uint16_t g_YTh[64 * NN];      // bf16 YT[n][k] = (X @ W2^T)[k][n]
__device__ float g_Wt[64 * 128];         // Wt[k][n] = W[n&63][(n>>6)*64 + k]
__device__ float g_XW1[NN * OO];         // X @ W1^T
__device__ float g_T[SPLITK][NN * OO];   // split-K partials of A @ YT^T
__device__ float g_degp[SPLITK][NN];     // split-K partials of rowsum(A)

__device__ __forceinline__ uint32_t smem_u32(const void* p) {
    uint32_t a;
    asm("{ .reg .u64 t; cvta.to.shared.u64 t, %1; cvt.u32.u64 %0, t; }" : "=r"(a) : "l"(p));
    return a;
}
__device__ __forceinline__ void mma_bf16(float* c, uint32_t a0, uint32_t a1, uint32_t a2,
                                         uint32_t a3, uint32_t b0, uint32_t b1) {
    asm volatile(
        "mma.sync.aligned.m16n8k16.row.col.f32.bf16.bf16.f32 "
        "{%0,%1,%2,%3}, {%4,%5,%6,%7}, {%8,%9}, {%0,%1,%2,%3};\n"
        : "+f"(c[0]), "+f"(c[1]), "+f"(c[2]), "+f"(c[3])
        : "r"(a0), "r"(a1), "r"(a2), "r"(a3), "r"(b0), "r"(b1));
}
#define CVT2(d, hi, lo) \
    asm("cvt.rn.bf16x2.f32 %0, %1, %2;" : "=r"(d) : "f"(hi), "f"(lo))
#define LDSM4(r0, r1, r2, r3, addr)                                              \
    asm volatile("ldmatrix.sync.aligned.m8n8.x4.shared.b16 {%0,%1,%2,%3}, [%4];" \
                 : "=r"(r0), "=r"(r1), "=r"(r2), "=r"(r3) : "r"(addr))
#define CPA16(dst, src) \
    asm volatile("cp.async.cg.shared.global [%0], [%1], 16;\n" :: "r"(dst), "l"(src))
#define CPCOMMIT() asm volatile("cp.async.commit_group;\n" ::: "memory")
#define CPWAIT(n)  asm volatile("cp.async.wait_group %0;\n" :: "n"(n) : "memory")

// ===================== kernel 0: W pre-transpose (once) =====================
__global__ void prep_w_kernel(const float* __restrict__ W) {
    int idx = blockIdx.x * 256 + threadIdx.x;   // 0..8191
    int o = idx >> 7, c = idx & 127;
    g_Wt[(c & 63) * 128 + (c >> 6) * 64 + o] = W[idx];
}

// ===================== kernel 1: projections (32 rows/block) — R12 version =====
#define WST_STRIDE 136
#define XST_STRIDE 34
#define YS_STRIDE  66
#define PROJ_SMEM ((64 * WST_STRIDE + 64 * XST_STRIDE + 32 * YS_STRIDE) * 4)

__global__ __launch_bounds__(256) void proj_kernel(const float* __restrict__ x) {
    extern __shared__ float s[];
    float* Wst = s;
    float* xst = Wst + 64 * WST_STRIDE;
    float* ys  = xst + 64 * XST_STRIDE;

    const int t  = threadIdx.x;
    const int i0 = blockIdx.x * 32;

#pragma unroll
    for (int j = 0; j < 8; ++j) {
        int idx4 = t + j * 256;
        int k = idx4 >> 5, n4 = (idx4 & 31) * 4;
        *(float4*)&Wst[k * WST_STRIDE + n4] = *(const float4*)&g_Wt[k * 128 + n4];
    }
#pragma unroll
    for (int j = 0; j < 8; ++j) {
        int idx = t + j * 256;
        int r = idx >> 6, k = idx & 63;
        xst[k * XST_STRIDE + r] = x[(size_t)(i0 + r) * FF + k];
    }
    __syncthreads();

    const int tx = t & 15;
    const int ty = t >> 4;

    float acc[2][8];
#pragma unroll
    for (int r = 0; r < 2; ++r)
#pragma unroll
        for (int j = 0; j < 8; ++j) acc[r][j] = 0.0f;

#pragma unroll
    for (int k = 0; k < 64; ++k) {
        float2 a  = *(const float2*)&xst[k * XST_STRIDE + 2 * ty];
        float4 b0 = *(const float4*)&Wst[k * WST_STRIDE + tx * 8];
        float4 b1 = *(const float4*)&Wst[k * WST_STRIDE + tx * 8 + 4];
        float av[2] = {a.x, a.y};
        float bv[8] = {b0.x, b0.y, b0.z, b0.w, b1.x, b1.y, b1.z, b1.w};
#pragma unroll
        for (int r = 0; r < 2; ++r)
#pragma unroll
            for (int j = 0; j < 8; ++j) acc[r][j] = fmaf(av[r], bv[j], acc[r][j]);
    }

    if (tx < 8) {
#pragma unroll
        for (int r = 0; r < 2; ++r) {
            size_t base = (size_t)(i0 + 2 * ty + r) * OO + tx * 8;
            *(float4*)&g_XW1[base]     = make_float4(acc[r][0], acc[r][1], acc[r][2], acc[r][3]);
            *(float4*)&g_XW1[base + 4] = make_float4(acc[r][4], acc[r][5], acc[r][6], acc[r][7]);
        }
    } else {
        int qb = (tx - 8) * 8;
#pragma unroll
        for (int r = 0; r < 2; ++r)
#pragma unroll
            for (int j = 0; j < 8; ++j)
                ys[(2 * ty + r) * YS_STRIDE + qb + j] = acc[r][j];
    }
    __syncthreads();

    {
        int col = t & 63, rb = (t >> 6) * 8;
        float v[8];
#pragma unroll
        for (int j = 0; j < 8; ++j) v[j] = ys[(rb + j) * YS_STRIDE + col];
        uint32_t u[4];
        CVT2(u[0], v[1], v[0]);
        CVT2(u[1], v[3], v[2]);
        CVT2(u[2], v[5], v[4]);
        CVT2(u[3], v[7], v[6]);
        *(uint4*)&g_YTh[(size_t)col * NN + i0 + rb] = make_uint4(u[0], u[1], u[2], u[3]);
    }
}

// ===================== kernel 2: split-K A@Y (BM=64, 128 thr, 4 CTAs/SM) ========
#define LDGA(buf, t_) do {                                                         \
    int k0 = (t_) * 32;                                                            \
    _Pragma("unroll")                                                              \
    for (int i_ = 0; i_ < 4; ++i_) {                                               \
        int idx = tid + i_ * 128;                                                  \
        buf[i_] = *(const float4*)(Abase + (size_t)(idx >> 3) * NN + k0 + (idx & 7) * 4); \
    }                                                                              \
} while (0)

#define STSA(buf, st) do {                                                         \
    uint2* base = (uint2*)((char*)sm + (st) * ASTG_B);                             \
    _Pragma("unroll")                                                              \
    for (int i_ = 0; i_ < 4; ++i_) {                                               \
        float4 v = buf[i_];                                                        \
        int idx = tid + i_ * 128;                                                  \
        dsum[i_] += (v.x + v.y) + (v.z + v.w);                                     \
        uint32_t lo, hi;                                                           \
        CVT2(lo, v.y, v.x); CVT2(hi, v.w, v.z);                                    \
        base[(idx >> 3) * 10 + (idx & 7)] = make_uint2(lo, hi);                    \
    }                                                                              \
} while (0)

#define MMA_STAGE(st) do {                                                         \
    uint32_t aB = aAddr + ((st) % NASTG) * ASTG_B;                                 \
    uint32_t bS = ((st) % NBSTG) * BSTG_B;                                         \
    _Pragma("unroll")                                                              \
    for (int s_ = 0; s_ < 2; ++s_) {                                               \
        uint32_t a_[4], b_[16];                                                    \
        LDSM4(a_[0], a_[1], a_[2], a_[3], aB + s_ * 32);                           \
        LDSM4(b_[0],  b_[1],  b_[2],  b_[3],  bOff[0] + bS + s_ * 32);             \
        LDSM4(b_[4],  b_[5],  b_[6],  b_[7],  bOff[1] + bS + s_ * 32);             \
        LDSM4(b_[8],  b_[9],  b_[10], b_[11], bOff[2] + bS + s_ * 32);             \
        LDSM4(b_[12], b_[13], b_[14], b_[15], bOff[3] + bS + s_ * 32);             \
        _Pragma("unroll")                                                          \
        for (int nt_ = 0; nt_ < 8; ++nt_)                                          \
            mma_bf16(acc[nt_], a_[0], a_[1], a_[2], a_[3],                         \
                     b_[(nt_ >> 1) * 4 + (nt_ & 1) * 2],                           \
                     b_[(nt_ >> 1) * 4 + (nt_ & 1) * 2 + 1]);                      \
    }                                                                              \
} while (0)

#define BODY(i_, FBX, FBY) do {                                                    \
    if ((i_) + 2 < NT) LDGA(FBX, (i_) + 2);                                        \
    CPWAIT(3);                                                                     \
    __syncthreads();                                                               \
    if ((i_) + PD < NT) {                                                          \
        int kk = ((i_) + PD) * 32;                                                 \
        uint32_t bd = bDst + (((i_) + PD) % NBSTG) * BSTG_B;                       \
        CPA16(bd,      Bsrc + kk);                                                 \
        CPA16(bd + 16, Bsrc + kk + 8);                                             \
    }                                                                              \
    CPCOMMIT();                                                                    \
    MMA_STAGE(i_);                                                                 \
    if ((i_) + 1 < NT) STSA(FBY, ((i_) + 1) % NASTG);                              \
} while (0)

__global__ __launch_bounds__(128, 4) void sage_mma_kernel(const float* __restrict__ A) {
    extern __shared__ uint32_t sm[];
    const uint32_t smA = smem_u32(sm);
    const int tid  = threadIdx.x;
    const int wid  = tid >> 5;
    const int lane = tid & 31;
    const int grp  = lane >> 2;
    const int kq   = lane & 3;
    const int m0   = wid * 16;

    const int mtile = blockIdx.x >> 2;       // 0..127
    const int kh    = blockIdx.x & 3;

    const float* Abase = A + (size_t)(mtile * BM) * NN + kh * KH;
    // B: thread covers n = tid>>1, two 16B chunks at c2, c2+1 (c2 = (tid&1)*2)
    const uint16_t* Bsrc = g_YTh + (size_t)(tid >> 1) * NN + kh * KH + (tid & 1) * 16;
    const uint32_t bDst = smA + BOFF + (tid >> 1) * AROW_B + (tid & 1) * 32;

    const uint32_t aAddr = smA + (m0 + (lane & 15)) * AROW_B + (lane >> 4) * 16;
    uint32_t bOff[4];
    {
        int mi = lane >> 3, rw = lane & 7;
#pragma unroll
        for (int j = 0; j < 4; ++j)
            bOff[j] = smA + BOFF + ((2 * j + (mi >> 1)) * 8 + rw) * AROW_B + (mi & 1) * 16;
    }

    float acc[8][4];
#pragma unroll
    for (int t = 0; t < 8; ++t)
#pragma unroll
        for (int r = 0; r < 4; ++r) acc[t][r] = 0.0f;
    float dsum[4] = {0.f, 0.f, 0.f, 0.f};

    float4 fb1[4], fb2[4];

    // prolog: B tiles 0..PD-1; A tile 0 -> stage 0; A tile 1 -> regs
#pragma unroll
    for (int t = 0; t < PD; ++t) {
        CPA16(bDst + t * BSTG_B,      Bsrc + t * 32);
        CPA16(bDst + t * BSTG_B + 16, Bsrc + t * 32 + 8);
        CPCOMMIT();
    }
    LDGA(fb1, 0);
    STSA(fb1, 0);
    LDGA(fb2, 1);

    for (int i = 0; i < NT; i += 2) {
        BODY(i,     fb1, fb2);
        BODY(i + 1, fb2, fb1);
    }

    // deg: rows (tid>>3) + i*16, 8 chunk-threads per row
#pragma unroll
    for (int i = 0; i < 4; ++i) {
        float d = dsum[i];
        d += __shfl_down_sync(0xFFFFFFFFu, d, 4);
        d += __shfl_down_sync(0xFFFFFFFFu, d, 2);
        d += __shfl_down_sync(0xFFFFFFFFu, d, 1);
        if ((lane & 7) == 0)
            g_degp[kh][mtile * BM + (tid >> 3) + i * 16] = d;
    }

    // store partial T
    float* dst = g_T[kh];
    int row_lo = mtile * BM + m0 + grp;
    int row_hi = row_lo + 8;
#pragma unroll
    for (int t = 0; t < 8; ++t) {
        int col = t * 8 + 2 * kq;
        *(float2*)&dst[(size_t)row_lo * OO + col] = make_float2(acc[t][0], acc[t][1]);
        *(float2*)&dst[(size_t)row_hi * OO + col] = make_float2(acc[t][2], acc[t][3]);
    }
}

// ===================== kernel 3: combine + epilogue (R12 version) ==============
__global__ __launch_bounds__(256) void epilogue_kernel(float* __restrict__ out) {
    int idx = blockIdx.x * blockDim.x + threadIdx.x;   // float4 index
    int r = idx >> 4;
    float deg = 1.0f;
    float4 tsum = make_float4(0.f, 0.f, 0.f, 0.f);
#pragma unroll
    for (int s = 0; s < SPLITK; ++s) {
        deg += g_degp[s][r];
        float4 v = *(const float4*)&g_T[s][(size_t)idx * 4];
        tsum.x += v.x; tsum.y += v.y; tsum.z += v.z; tsum.w += v.w;
    }
    float inv = 1.0f / deg;
    float4 xw = *(const float4*)&g_XW1[(size_t)idx * 4];
    *(float4*)&out[(size_t)idx * 4] =
        make_float4(xw.x + tsum.x * inv, xw.y + tsum.y * inv,
                    xw.z + tsum.z * inv, xw.w + tsum.w * inv);
}

// -------------------- launch --------------------
extern "C" void kernel_launch(void* const* d_in, const int* in_sizes, int n_in,
                              void* d_out, int out_size) {
    const float* adj      = (const float*)d_in[0];  // [8192, 8192]
    const float* features = (const float*)d_in[1];  // [8192, 64]
    const float* W        = (const float*)d_in[2];  // [64, 128]
    float* out            = (float*)d_out;          // [8192, 64]

    cudaFuncSetAttribute(proj_kernel,
                         cudaFuncAttributeMaxDynamicSharedMemorySize, PROJ_SMEM);
    cudaFuncSetAttribute(sage_mma_kernel,
                         cudaFuncAttributeMaxDynamicSharedMemorySize, SMEM_MAIN);

    prep_w_kernel<<<32, 256>>>(W);
    proj_kernel<<<NN / 32, 256, PROJ_SMEM>>>(features);
    sage_mma_kernel<<<SPLITK * (NN / BM), 128, SMEM_MAIN>>>(adj);
    epilogue_kernel<<<(NN * OO / 4) / 256, 256>>>(out);
}

// round 16
// speedup vs baseline: 1.1624x; 1.1624x over previous
#include <cuda_runtime.h>
#include <cstdint>

#define NN 8192
#define FF 64
#define OO 64
#define BM 128
#define SPLITK 4
#define KH (NN / SPLITK)        // 2048
#define NT (KH / 32)            // 64 k-tiles per CTA

// A smem: bf16, 128 rows x 80B (16 data words + 4 pad), 3 stages
#define AROW_B 80
#define ASTG_B (BM * AROW_B)    // 10240
#define NASTG 3
// B smem: bf16, 64 rows x 80B, 5 stages, prefetch distance 4
#define BOFF   (NASTG * ASTG_B) // 30720
#define BSTG_B (64 * AROW_B)    // 5120
#define NBSTG 5
#define PD 4
#define SMEM_MAIN (BOFF + NBSTG * BSTG_B)   // 56320

// -------------------- scratch --------------------
__device__ uint16_t g_YTh[64 * NN];      // bf16 YT[n][k] = (X @ W2^T)[k][n]
__device__ float g_Wt[64 * 128];         // Wt[k][n] = W[n&63][(n>>6)*64 + k]
__device__ float g_T[SPLITK][NN * OO];   // split-K partials of A @ YT^T
__device__ float g_degp[SPLITK][NN];     // split-K partials of rowsum(A)

__device__ __forceinline__ uint32_t smem_u32(const void* p) {
    uint32_t a;
    asm("{ .reg .u64 t; cvta.to.shared.u64 t, %1; cvt.u32.u64 %0, t; }" : "=r"(a) : "l"(p));
    return a;
}
__device__ __forceinline__ void mma_bf16(float* c, uint32_t a0, uint32_t a1, uint32_t a2,
                                         uint32_t a3, uint32_t b0, uint32_t b1) {
    asm volatile(
        "mma.sync.aligned.m16n8k16.row.col.f32.bf16.bf16.f32 "
        "{%0,%1,%2,%3}, {%4,%5,%6,%7}, {%8,%9}, {%0,%1,%2,%3};\n"
        : "+f"(c[0]), "+f"(c[1]), "+f"(c[2]), "+f"(c[3])
        : "r"(a0), "r"(a1), "r"(a2), "r"(a3), "r"(b0), "r"(b1));
}
#define CVT2(d, hi, lo) \
    asm("cvt.rn.bf16x2.f32 %0, %1, %2;" : "=r"(d) : "f"(hi), "f"(lo))
#define LDSM4(r0, r1, r2, r3, addr)                                              \
    asm volatile("ldmatrix.sync.aligned.m8n8.x4.shared.b16 {%0,%1,%2,%3}, [%4];" \
                 : "=r"(r0), "=r"(r1), "=r"(r2), "=r"(r3) : "r"(addr))
#define CPA16(dst, src) \
    asm volatile("cp.async.cg.shared.global [%0], [%1], 16;\n" :: "r"(dst), "l"(src))
#define CPCOMMIT() asm volatile("cp.async.commit_group;\n" ::: "memory")
#define CPWAIT(n)  asm volatile("cp.async.wait_group %0;\n" :: "n"(n) : "memory")

// ===================== kernel 0: W pre-transpose (once) =====================
__global__ void prep_w_kernel(const float* __restrict__ W) {
    int idx = blockIdx.x * 256 + threadIdx.x;   // 0..8191
    int o = idx >> 7, c = idx & 127;
    g_Wt[(c & 63) * 128 + (c >> 6) * 64 + o] = W[idx];
}

// ===================== kernel 1: Y projection only (32 rows/block) =============
#define W2ST 68
#define XST_STRIDE 34
#define YS_STRIDE  66
#define PROJ_SMEM ((64 * W2ST + 64 * XST_STRIDE + 32 * YS_STRIDE) * 4)

__global__ __launch_bounds__(256) void proj_kernel(const float* __restrict__ x) {
    extern __shared__ float s[];
    float* W2st = s;                          // W2st[k][n] = g_Wt[k][64+n]
    float* xst  = W2st + 64 * W2ST;           // xst[k][r] = x[i0+r][k]
    float* ys   = xst + 64 * XST_STRIDE;      // ys[r][q]  = Y[i0+r][q]

    const int t  = threadIdx.x;
    const int i0 = blockIdx.x * 32;

    // stage W2 (64k x 64n), coalesced float4 from g_Wt
#pragma unroll
    for (int j = 0; j < 4; ++j) {
        int idx4 = t + j * 256;               // 0..1023
        int k = idx4 >> 4, n4 = (idx4 & 15) * 4;
        *(float4*)&W2st[k * W2ST + n4] = *(const float4*)&g_Wt[k * 128 + 64 + n4];
    }
    // stage x transposed (32 rows x 64 cols)
#pragma unroll
    for (int j = 0; j < 8; ++j) {
        int idx = t + j * 256;                // 0..2047
        int r = idx >> 6, k = idx & 63;
        xst[k * XST_STRIDE + r] = x[(size_t)(i0 + r) * FF + k];
    }
    __syncthreads();

    const int tx = t & 7;                     // col group tx*8
    const int ty = t >> 3;                    // row 0..31

    float acc[8];
#pragma unroll
    for (int j = 0; j < 8; ++j) acc[j] = 0.0f;

#pragma unroll
    for (int k = 0; k < 64; ++k) {
        float a   = xst[k * XST_STRIDE + ty];
        float4 b0 = *(const float4*)&W2st[k * W2ST + tx * 8];
        float4 b1 = *(const float4*)&W2st[k * W2ST + tx * 8 + 4];
        acc[0] = fmaf(a, b0.x, acc[0]); acc[1] = fmaf(a, b0.y, acc[1]);
        acc[2] = fmaf(a, b0.z, acc[2]); acc[3] = fmaf(a, b0.w, acc[3]);
        acc[4] = fmaf(a, b1.x, acc[4]); acc[5] = fmaf(a, b1.y, acc[5]);
        acc[6] = fmaf(a, b1.z, acc[6]); acc[7] = fmaf(a, b1.w, acc[7]);
    }

#pragma unroll
    for (int j = 0; j < 8; ++j) ys[ty * YS_STRIDE + tx * 8 + j] = acc[j];
    __syncthreads();

    // YT write: col = t&63 (n), k-rows rb..rb+7, packed bf16 (16B store)
    {
        int col = t & 63, rb = (t >> 6) * 8;
        float v[8];
#pragma unroll
        for (int j = 0; j < 8; ++j) v[j] = ys[(rb + j) * YS_STRIDE + col];
        uint32_t u[4];
        CVT2(u[0], v[1], v[0]);
        CVT2(u[1], v[3], v[2]);
        CVT2(u[2], v[5], v[4]);
        CVT2(u[3], v[7], v[6]);
        *(uint4*)&g_YTh[(size_t)col * NN + i0 + rb] = make_uint4(u[0], u[1], u[2], u[3]);
    }
}

// ===================== kernel 2: split-K A@Y — byte-identical to R12 ==========
#define LDGA(buf, t_) do {                                                         \
    int k0 = (t_) * 32;                                                            \
    _Pragma("unroll")                                                              \
    for (int i_ = 0; i_ < 4; ++i_) {                                               \
        int idx = tid + i_ * 256;                                                  \
        buf[i_] = *(const float4*)(Abase + (size_t)(idx >> 3) * NN + k0 + (idx & 7) * 4); \
    }                                                                              \
} while (0)

#define STSA(buf, st) do {                                                         \
    uint2* base = (uint2*)((char*)sm + (st) * ASTG_B);                             \
    _Pragma("unroll")                                                              \
    for (int i_ = 0; i_ < 4; ++i_) {                                               \
        float4 v = buf[i_];                                                        \
        int idx = tid + i_ * 256;                                                  \
        dsum[i_] += (v.x + v.y) + (v.z + v.w);                                     \
        uint32_t lo, hi;                                                           \
        CVT2(lo, v.y, v.x); CVT2(hi, v.w, v.z);                                    \
        base[(idx >> 3) * 10 + (idx & 7)] = make_uint2(lo, hi);                    \
    }                                                                              \
} while (0)

#define MMA_STAGE(st) do {                                                         \
    uint32_t aB = aAddr + ((st) % NASTG) * ASTG_B;                                 \
    uint32_t bS = ((st) % NBSTG) * BSTG_B;                                         \
    _Pragma("unroll")                                                              \
    for (int s_ = 0; s_ < 2; ++s_) {                                               \
        uint32_t a_[4], b_[16];                                                    \
        LDSM4(a_[0], a_[1], a_[2], a_[3], aB + s_ * 32);                           \
        LDSM4(b_[0],  b_[1],  b_[2],  b_[3],  bOff[0] + bS + s_ * 32);             \
        LDSM4(b_[4],  b_[5],  b_[6],  b_[7],  bOff[1] + bS + s_ * 32);             \
        LDSM4(b_[8],  b_[9],  b_[10], b_[11], bOff[2] + bS + s_ * 32);             \
        LDSM4(b_[12], b_[13], b_[14], b_[15], bOff[3] + bS + s_ * 32);             \
        _Pragma("unroll")                                                          \
        for (int nt_ = 0; nt_ < 8; ++nt_)                                          \
            mma_bf16(acc[nt_], a_[0], a_[1], a_[2], a_[3],                         \
                     b_[(nt_ >> 1) * 4 + (nt_ & 1) * 2],                           \
                     b_[(nt_ >> 1) * 4 + (nt_ & 1) * 2 + 1]);                      \
    }                                                                              \
} while (0)

#define BODY(i_, FBX, FBY) do {                                                    \
    if ((i_) + 2 < NT) LDGA(FBX, (i_) + 2);                                        \
    CPWAIT(3);                                                                     \
    __syncthreads();                                                               \
    if ((i_) + PD < NT)                                                            \
        CPA16(bDst + (((i_) + PD) % NBSTG) * BSTG_B, Bsrc + ((i_) + PD) * 32);     \
    CPCOMMIT();                                                                    \
    MMA_STAGE(i_);                                                                 \
    if ((i_) + 1 < NT) STSA(FBY, ((i_) + 1) % NASTG);                              \
} while (0)

__global__ __launch_bounds__(256, 2) void sage_mma_kernel(const float* __restrict__ A) {
    extern __shared__ uint32_t sm[];
    const uint32_t smA = smem_u32(sm);
    const int tid  = threadIdx.x;
    const int wid  = tid >> 5;
    const int lane = tid & 31;
    const int grp  = lane >> 2;
    const int kq   = lane & 3;
    const int m0   = wid * 16;

    const int mtile = blockIdx.x >> 2;
    const int kh    = blockIdx.x & 3;

    const float* Abase = A + (size_t)(mtile * BM) * NN + kh * KH;
    const uint16_t* Bsrc = g_YTh + (size_t)(tid >> 2) * NN + kh * KH + (tid & 3) * 8;
    const uint32_t bDst = smA + BOFF + (tid >> 2) * AROW_B + (tid & 3) * 16;

    const uint32_t aAddr = smA + (m0 + (lane & 15)) * AROW_B + (lane >> 4) * 16;
    uint32_t bOff[4];
    {
        int mi = lane >> 3, rw = lane & 7;
#pragma unroll
        for (int j = 0; j < 4; ++j)
            bOff[j] = smA + BOFF + ((2 * j + (mi >> 1)) * 8 + rw) * AROW_B + (mi & 1) * 16;
    }

    float acc[8][4];
#pragma unroll
    for (int t = 0; t < 8; ++t)
#pragma unroll
        for (int r = 0; r < 4; ++r) acc[t][r] = 0.0f;
    float dsum[4] = {0.f, 0.f, 0.f, 0.f};

    float4 fb1[4], fb2[4];

#pragma unroll
    for (int t = 0; t < PD; ++t) {
        CPA16(bDst + t * BSTG_B, Bsrc + t * 32);
        CPCOMMIT();
    }
    LDGA(fb1, 0);
    STSA(fb1, 0);
    LDGA(fb2, 1);

    for (int i = 0; i < NT; i += 2) {
        BODY(i,     fb1, fb2);
        BODY(i + 1, fb2, fb1);
    }

#pragma unroll
    for (int i = 0; i < 4; ++i) {
        float d = dsum[i];
        d += __shfl_down_sync(0xFFFFFFFFu, d, 4);
        d += __shfl_down_sync(0xFFFFFFFFu, d, 2);
        d += __shfl_down_sync(0xFFFFFFFFu, d, 1);
        if ((lane & 7) == 0)
            g_degp[kh][mtile * BM + (tid >> 3) + i * 32] = d;
    }

    float* dst = g_T[kh];
    int row_lo = mtile * BM + m0 + grp;
    int row_hi = row_lo + 8;
#pragma unroll
    for (int t = 0; t < 8; ++t) {
        int col = t * 8 + 2 * kq;
        *(float2*)&dst[(size_t)row_lo * OO + col] = make_float2(acc[t][0], acc[t][1]);
        *(float2*)&dst[(size_t)row_hi * OO + col] = make_float2(acc[t][2], acc[t][3]);
    }
}

// ===================== kernel 3: fused XW1 + combine + epilogue ===============
#define EW 68
#define EXS 17
#define EPI_SMEM ((64 * EW + 64 * EXS) * 4)   // ~21.8 KB

__global__ __launch_bounds__(256) void epilogue_kernel(const float* __restrict__ x,
                                                       float* __restrict__ out) {
    extern __shared__ float es[];
    float* W1st = es;                 // W1st[k][n], n 0..63
    float* xst  = W1st + 64 * EW;     // xst[k][r], r 0..15

    const int t  = threadIdx.x;
    const int R0 = blockIdx.x * 16;

    // stage W1 (coalesced float4)
#pragma unroll
    for (int j = 0; j < 4; ++j) {
        int idx4 = t + j * 256;               // 0..1023
        int k = idx4 >> 4, n4 = (idx4 & 15) * 4;
        *(float4*)&W1st[k * EW + n4] = *(const float4*)&g_Wt[k * 128 + n4];
    }
    // stage x (16 rows, transposed)
#pragma unroll
    for (int j = 0; j < 4; ++j) {
        int idx = t + j * 256;                // 0..1023
        int r = idx >> 6, k = idx & 63;
        xst[k * EXS + r] = x[(size_t)(R0 + r) * FF + k];
    }
    __syncthreads();

    const int rl = t >> 4;                    // 0..15
    const int c4 = (t & 15) * 4;              // col base

    float4 acc = make_float4(0.f, 0.f, 0.f, 0.f);
#pragma unroll
    for (int k = 0; k < 64; ++k) {
        float a  = xst[k * EXS + rl];
        float4 b = *(const float4*)&W1st[k * EW + c4];
        acc.x = fmaf(a, b.x, acc.x);
        acc.y = fmaf(a, b.y, acc.y);
        acc.z = fmaf(a, b.z, acc.z);
        acc.w = fmaf(a, b.w, acc.w);
    }

    const int r = R0 + rl;
    const size_t idx4g = (size_t)r * 16 + (t & 15);
    float deg = 1.0f;
    float4 tsum = make_float4(0.f, 0.f, 0.f, 0.f);
#pragma unroll
    for (int s = 0; s < SPLITK; ++s) {
        deg += g_degp[s][r];
        float4 v = *(const float4*)&g_T[s][idx4g * 4];
        tsum.x += v.x; tsum.y += v.y; tsum.z += v.z; tsum.w += v.w;
    }
    float inv = 1.0f / deg;
    *(float4*)&out[idx4g * 4] =
        make_float4(acc.x + tsum.x * inv, acc.y + tsum.y * inv,
                    acc.z + tsum.z * inv, acc.w + tsum.w * inv);
}

// -------------------- launch --------------------
extern "C" void kernel_launch(void* const* d_in, const int* in_sizes, int n_in,
                              void* d_out, int out_size) {
    const float* adj      = (const float*)d_in[0];  // [8192, 8192]
    const float* features = (const float*)d_in[1];  // [8192, 64]
    const float* W        = (const float*)d_in[2];  // [64, 128]
    float* out            = (float*)d_out;          // [8192, 64]

    cudaFuncSetAttribute(proj_kernel,
                         cudaFuncAttributeMaxDynamicSharedMemorySize, PROJ_SMEM);
    cudaFuncSetAttribute(sage_mma_kernel,
                         cudaFuncAttributeMaxDynamicSharedMemorySize, SMEM_MAIN);
    cudaFuncSetAttribute(epilogue_kernel,
                         cudaFuncAttributeMaxDynamicSharedMemorySize, EPI_SMEM);

    prep_w_kernel<<<32, 256>>>(W);
    proj_kernel<<<NN / 32, 256, PROJ_SMEM>>>(features);
    sage_mma_kernel<<<SPLITK * (NN / BM), 256, SMEM_MAIN>>>(adj);
    epilogue_kernel<<<NN / 16, 256, EPI_SMEM>>>(features, out);
}